// round 3
// baseline (speedup 1.0000x reference)
#include <cuda_runtime.h>
#include <math.h>

#define VOCAB 32000
#define EMB   32
#define HID   8
#define SEQ   64
#define BATCH 64
#define NROWS (SEQ*BATCH)   /* 4096 */

typedef unsigned long long u64;

__device__ __forceinline__ u64 ffma2(u64 a, u64 b, u64 c) {
    u64 d; asm("fma.rn.f32x2 %0, %1, %2, %3;" : "=l"(d) : "l"(a), "l"(b), "l"(c)); return d;
}
__device__ __forceinline__ u64 fadd2(u64 a, u64 b) {
    u64 d; asm("add.rn.f32x2 %0, %1, %2;" : "=l"(d) : "l"(a), "l"(b)); return d;
}
__device__ __forceinline__ u64 pack2(float x, float y) {
    u64 d; asm("mov.b64 %0, {%1, %2};" : "=l"(d) : "r"(__float_as_uint(x)), "r"(__float_as_uint(y))); return d;
}
__device__ __forceinline__ void unpack2(u64 v, float& x, float& y) {
    unsigned a, b; asm("mov.b64 {%0, %1}, %2;" : "=r"(a), "=r"(b) : "l"(v));
    x = __uint_as_float(a); y = __uint_as_float(b);
}
__device__ __forceinline__ float tanh_fast(float x) {
    float y; asm("tanh.approx.f32 %0, %1;" : "=f"(y) : "f"(x)); return y;
}

// Scratch (device globals: allocation-free rule)
__device__ float g_A[2*SEQ*BATCH*10];   // per-dir, per-(t,b): [az, ar, ah0..7] from e-part
__device__ float g_h[NROWS*16];         // total_h: [t][b][dir*8+j]
__device__ float g_sum[NROWS];          // sum of exp(logit) per row

// ---------------------------------------------------------------------------
// Kernel 0: embedding gather + input-projection precompute (parallel GRU part)
// ---------------------------------------------------------------------------
__global__ __launch_bounds__(64) void k_pre(
    const int*   __restrict__ x,   const float* __restrict__ emb,
    const float* __restrict__ Wz1, const float* __restrict__ bz1,
    const float* __restrict__ Wr1, const float* __restrict__ br1,
    const float* __restrict__ Wh1, const float* __restrict__ bh1,
    const float* __restrict__ Wz2, const float* __restrict__ bz2,
    const float* __restrict__ Wr2, const float* __restrict__ br2,
    const float* __restrict__ Wh2, const float* __restrict__ bh2)
{
    int t = blockIdx.x, dir = blockIdx.y, b = threadIdx.x;
    int gid = (dir*SEQ + t)*BATCH + b;
    if (gid < NROWS) g_sum[gid] = 0.f;

    const float* Wz = dir ? Wz2 : Wz1;
    const float* Wr = dir ? Wr2 : Wr1;
    const float* Wh = dir ? Wh2 : Wh1;
    float az = (dir ? bz2 : bz1)[0];
    float ar = (dir ? br2 : br1)[0];
    const float* bh = dir ? bh2 : bh1;
    float ah[8];
    #pragma unroll
    for (int j = 0; j < 8; j++) ah[j] = bh[j];

    int idx = x[t*BATCH + b];
    const float* e = emb + (size_t)idx * EMB;
    float ev[32];
    #pragma unroll
    for (int k = 0; k < 8; k++) {
        float4 v4 = ((const float4*)e)[k];
        ev[4*k+0] = v4.x; ev[4*k+1] = v4.y; ev[4*k+2] = v4.z; ev[4*k+3] = v4.w;
    }
    #pragma unroll
    for (int k = 0; k < 32; k++) {
        float evk = ev[k];
        az += evk * Wz[8 + k];
        ar += evk * Wr[8 + k];
        #pragma unroll
        for (int j = 0; j < 8; j++) ah[j] += evk * Wh[(8 + k)*8 + j];
    }
    float* Ab = g_A + (size_t)((dir*SEQ + t)*10)*BATCH + b;
    Ab[0] = az;
    Ab[BATCH] = ar;
    #pragma unroll
    for (int j = 0; j < 8; j++) Ab[(2 + j)*BATCH] = ah[j];
}

// ---------------------------------------------------------------------------
// Kernel 1: serial GRU. 128 threads = 2 dirs x 64 batches. A[t+1] prefetched
// into registers while step t computes. tanh.approx.
// ---------------------------------------------------------------------------
__global__ __launch_bounds__(128) void k_gru(
    const float* __restrict__ Wz1, const float* __restrict__ Wr1, const float* __restrict__ Wh1,
    const float* __restrict__ Wz2, const float* __restrict__ Wr2, const float* __restrict__ Wh2)
{
    int tid = threadIdx.x;
    int dir = tid >> 6, b = tid & 63;
    const float* Wz = dir ? Wz2 : Wz1;
    const float* Wr = dir ? Wr2 : Wr1;
    const float* Wh = dir ? Wh2 : Wh1;

    float wz[8], wr[8], wh[64];
    #pragma unroll
    for (int i = 0; i < 8; i++) { wz[i] = Wz[i]; wr[i] = Wr[i]; }
    #pragma unroll
    for (int i = 0; i < 64; i++) wh[i] = Wh[i];

    float h[8];
    #pragma unroll
    for (int j = 0; j < 8; j++) h[j] = 0.f;

    int time0 = dir ? (SEQ - 1) : 0;
    float a[10];
    {
        const float* A = g_A + (size_t)((dir*SEQ + time0)*10)*BATCH + b;
        #pragma unroll
        for (int i = 0; i < 10; i++) a[i] = A[i*BATCH];
    }

    for (int step = 0; step < SEQ; ++step) {
        int time = dir ? (SEQ - 1 - step) : step;

        float an[10];
        if (step < SEQ - 1) {
            int ntime = dir ? (SEQ - 2 - step) : (step + 1);
            const float* A = g_A + (size_t)((dir*SEQ + ntime)*10)*BATCH + b;
            #pragma unroll
            for (int i = 0; i < 10; i++) an[i] = A[i*BATCH];
        }

        float* gh = g_h + (size_t)(time*BATCH + b)*16 + dir*8;
        ((float4*)gh)[0] = make_float4(h[0], h[1], h[2], h[3]);
        ((float4*)gh)[1] = make_float4(h[4], h[5], h[6], h[7]);

        float zi = a[0], ri = a[1];
        #pragma unroll
        for (int i = 0; i < 8; i++) { zi += h[i]*wz[i]; ri += h[i]*wr[i]; }
        float z = 1.f / (1.f + __expf(-zi));
        float r = 1.f / (1.f + __expf(-ri));
        float rh[8];
        #pragma unroll
        for (int i = 0; i < 8; i++) rh[i] = r * h[i];
        float hc[8];
        #pragma unroll
        for (int j = 0; j < 8; j++) {
            float s = a[2 + j];
            #pragma unroll
            for (int i = 0; i < 8; i++) s += rh[i] * wh[i*8 + j];
            hc[j] = tanh_fast(s);
        }
        #pragma unroll
        for (int j = 0; j < 8; j++) h[j] += z * (hc[j] - h[j]);

        #pragma unroll
        for (int i = 0; i < 10; i++) a[i] = an[i];
    }
}

// ---------------------------------------------------------------------------
// Kernels 2a/2b: logits + log_softmax, FFMA2, low-register tiling.
// Block = 32 rows x 1280 vocab; warp owns 4 rows; thread owns 4 consecutive v.
// 8 u64 accumulators/thread -> ~56 regs -> 4 blocks/SM.
// ---------------------------------------------------------------------------
__global__ __launch_bounds__(256, 4) void k_sumexp(
    const float* __restrict__ Wout, const float* __restrict__ bout)
{
    __shared__ u64 h_pack[32*16];
    int tid = threadIdx.x;
    int by  = blockIdx.y;                 // rows by*32 .. by*32+31
    for (int i = tid; i < 32*16; i += 256) {
        float v = g_h[(size_t)by*512 + i];
        h_pack[i] = pack2(v, v);
    }
    __syncthreads();

    int warp = tid >> 5, lane = tid & 31;
    const u64* hp = h_pack + warp*4*16;   // 4 rows for this warp
    float part[4] = {0.f, 0.f, 0.f, 0.f};

    int vbase = blockIdx.x*1280 + lane*4;
    for (int it = 0; it < 10; ++it) {
        int v = vbase + it*128;
        ulonglong2 bo = *(const ulonglong2*)(bout + v);
        u64 a0[4], a1[4];
        #pragma unroll
        for (int r = 0; r < 4; r++) { a0[r] = bo.x; a1[r] = bo.y; }
        #pragma unroll
        for (int k = 0; k < 16; k++) {
            ulonglong2 wv = *(const ulonglong2*)(Wout + (size_t)k*VOCAB + v);
            #pragma unroll
            for (int r = 0; r < 4; r++) {
                u64 h2 = hp[r*16 + k];
                a0[r] = ffma2(wv.x, h2, a0[r]);
                a1[r] = ffma2(wv.y, h2, a1[r]);
            }
        }
        #pragma unroll
        for (int r = 0; r < 4; r++) {
            float e0, e1, e2, e3;
            unpack2(a0[r], e0, e1);
            unpack2(a1[r], e2, e3);
            part[r] += __expf(e0) + __expf(e1) + __expf(e2) + __expf(e3);
        }
    }
    #pragma unroll
    for (int r = 0; r < 4; r++) {
        float p = part[r];
        #pragma unroll
        for (int off = 16; off > 0; off >>= 1)
            p += __shfl_xor_sync(0xffffffffu, p, off);
        if (lane == 0) atomicAdd(&g_sum[by*32 + warp*4 + r], p);
    }
}

__global__ __launch_bounds__(256, 4) void k_write(
    const float* __restrict__ Wout, const float* __restrict__ bout,
    float* __restrict__ out)
{
    __shared__ u64 h_pack[32*16];
    __shared__ u64 nls_sh[32];
    int tid = threadIdx.x;
    int by  = blockIdx.y;
    for (int i = tid; i < 32*16; i += 256) {
        float v = g_h[(size_t)by*512 + i];
        h_pack[i] = pack2(v, v);
    }
    if (tid < 32) {
        float nls = -__logf(g_sum[by*32 + tid]);
        nls_sh[tid] = pack2(nls, nls);
    }
    __syncthreads();

    int warp = tid >> 5, lane = tid & 31;
    const u64* hp = h_pack + warp*4*16;
    u64 nls[4];
    #pragma unroll
    for (int r = 0; r < 4; r++) nls[r] = nls_sh[warp*4 + r];

    int row_base = by*32 + warp*4;
    int vbase = blockIdx.x*1280 + lane*4;
    for (int it = 0; it < 10; ++it) {
        int v = vbase + it*128;
        ulonglong2 bo = *(const ulonglong2*)(bout + v);
        u64 a0[4], a1[4];
        #pragma unroll
        for (int r = 0; r < 4; r++) { a0[r] = bo.x; a1[r] = bo.y; }
        #pragma unroll
        for (int k = 0; k < 16; k++) {
            ulonglong2 wv = *(const ulonglong2*)(Wout + (size_t)k*VOCAB + v);
            #pragma unroll
            for (int r = 0; r < 4; r++) {
                u64 h2 = hp[r*16 + k];
                a0[r] = ffma2(wv.x, h2, a0[r]);
                a1[r] = ffma2(wv.y, h2, a1[r]);
            }
        }
        #pragma unroll
        for (int r = 0; r < 4; r++) {
            u64 o0 = fadd2(a0[r], nls[r]);
            u64 o1 = fadd2(a1[r], nls[r]);
            float* p = out + (size_t)(row_base + r)*VOCAB + v;
            asm volatile("st.global.cs.v2.u64 [%0], {%1, %2};"
                         :: "l"(p), "l"(o0), "l"(o1) : "memory");
        }
    }
}

// ---------------------------------------------------------------------------
extern "C" void kernel_launch(void* const* d_in, const int* in_sizes, int n_in,
                              void* d_out, int out_size)
{
    const int*   x    = (const int*)  d_in[0];
    const float* emb  = (const float*)d_in[1];
    const float* Wz1  = (const float*)d_in[2];  const float* bz1 = (const float*)d_in[3];
    const float* Wr1  = (const float*)d_in[4];  const float* br1 = (const float*)d_in[5];
    const float* Wh1  = (const float*)d_in[6];  const float* bh1 = (const float*)d_in[7];
    const float* Wz2  = (const float*)d_in[8];  const float* bz2 = (const float*)d_in[9];
    const float* Wr2  = (const float*)d_in[10]; const float* br2 = (const float*)d_in[11];
    const float* Wh2  = (const float*)d_in[12]; const float* bh2 = (const float*)d_in[13];
    const float* Wout = (const float*)d_in[14]; const float* bout= (const float*)d_in[15];
    float* out = (float*)d_out;

    k_pre<<<dim3(SEQ, 2), BATCH>>>(x, emb, Wz1, bz1, Wr1, br1, Wh1, bh1,
                                   Wz2, bz2, Wr2, br2, Wh2, bh2);
    k_gru<<<1, 128>>>(Wz1, Wr1, Wh1, Wz2, Wr2, Wh2);
    k_sumexp<<<dim3(25, 128), 256>>>(Wout, bout);
    k_write <<<dim3(25, 128), 256>>>(Wout, bout, out);
}

// round 4
// speedup vs baseline: 1.1365x; 1.1365x over previous
#include <cuda_runtime.h>
#include <math.h>

#define VOCAB 32000
#define EMB   32
#define HID   8
#define SEQ   64
#define BATCH 64
#define NROWS (SEQ*BATCH)   /* 4096 */

typedef unsigned long long u64;

__device__ __forceinline__ u64 ffma2(u64 a, u64 b, u64 c) {
    u64 d; asm("fma.rn.f32x2 %0, %1, %2, %3;" : "=l"(d) : "l"(a), "l"(b), "l"(c)); return d;
}
__device__ __forceinline__ u64 fadd2(u64 a, u64 b) {
    u64 d; asm("add.rn.f32x2 %0, %1, %2;" : "=l"(d) : "l"(a), "l"(b)); return d;
}
__device__ __forceinline__ u64 pack2(float x, float y) {
    u64 d; asm("mov.b64 %0, {%1, %2};" : "=l"(d) : "r"(__float_as_uint(x)), "r"(__float_as_uint(y))); return d;
}
__device__ __forceinline__ void unpack2(u64 v, float& x, float& y) {
    unsigned a, b; asm("mov.b64 {%0, %1}, %2;" : "=r"(a), "=r"(b) : "l"(v));
    x = __uint_as_float(a); y = __uint_as_float(b);
}
__device__ __forceinline__ float tanh_fast(float x) {
    float y; asm("tanh.approx.f32 %0, %1;" : "=f"(y) : "f"(x)); return y;
}

// Scratch (device globals: allocation-free rule)
__device__ float g_A[2*SEQ*BATCH*10];
__device__ float g_h[NROWS*16];
__device__ float g_sum[NROWS];

// ---------------------------------------------------------------------------
// Kernel 0: embedding gather + input-projection precompute
// ---------------------------------------------------------------------------
__global__ __launch_bounds__(64) void k_pre(
    const int*   __restrict__ x,   const float* __restrict__ emb,
    const float* __restrict__ Wz1, const float* __restrict__ bz1,
    const float* __restrict__ Wr1, const float* __restrict__ br1,
    const float* __restrict__ Wh1, const float* __restrict__ bh1,
    const float* __restrict__ Wz2, const float* __restrict__ bz2,
    const float* __restrict__ Wr2, const float* __restrict__ br2,
    const float* __restrict__ Wh2, const float* __restrict__ bh2)
{
    int t = blockIdx.x, dir = blockIdx.y, b = threadIdx.x;
    int gid = (dir*SEQ + t)*BATCH + b;
    if (gid < NROWS) g_sum[gid] = 0.f;

    const float* Wz = dir ? Wz2 : Wz1;
    const float* Wr = dir ? Wr2 : Wr1;
    const float* Wh = dir ? Wh2 : Wh1;
    float az = (dir ? bz2 : bz1)[0];
    float ar = (dir ? br2 : br1)[0];
    const float* bh = dir ? bh2 : bh1;
    float ah[8];
    #pragma unroll
    for (int j = 0; j < 8; j++) ah[j] = bh[j];

    int idx = x[t*BATCH + b];
    const float* e = emb + (size_t)idx * EMB;
    float ev[32];
    #pragma unroll
    for (int k = 0; k < 8; k++) {
        float4 v4 = ((const float4*)e)[k];
        ev[4*k+0] = v4.x; ev[4*k+1] = v4.y; ev[4*k+2] = v4.z; ev[4*k+3] = v4.w;
    }
    #pragma unroll
    for (int k = 0; k < 32; k++) {
        float evk = ev[k];
        az += evk * Wz[8 + k];
        ar += evk * Wr[8 + k];
        #pragma unroll
        for (int j = 0; j < 8; j++) ah[j] += evk * Wh[(8 + k)*8 + j];
    }
    float* Ab = g_A + (size_t)((dir*SEQ + t)*10)*BATCH + b;
    Ab[0] = az;
    Ab[BATCH] = ar;
    #pragma unroll
    for (int j = 0; j < 8; j++) Ab[(2 + j)*BATCH] = ah[j];
}

// ---------------------------------------------------------------------------
// Kernel 1: serial GRU, 2 dirs x 64 batches, prefetch A[t+1].
// ---------------------------------------------------------------------------
__global__ __launch_bounds__(128) void k_gru(
    const float* __restrict__ Wz1, const float* __restrict__ Wr1, const float* __restrict__ Wh1,
    const float* __restrict__ Wz2, const float* __restrict__ Wr2, const float* __restrict__ Wh2)
{
    int tid = threadIdx.x;
    int dir = tid >> 6, b = tid & 63;
    const float* Wz = dir ? Wz2 : Wz1;
    const float* Wr = dir ? Wr2 : Wr1;
    const float* Wh = dir ? Wh2 : Wh1;

    float wz[8], wr[8], wh[64];
    #pragma unroll
    for (int i = 0; i < 8; i++) { wz[i] = Wz[i]; wr[i] = Wr[i]; }
    #pragma unroll
    for (int i = 0; i < 64; i++) wh[i] = Wh[i];

    float h[8];
    #pragma unroll
    for (int j = 0; j < 8; j++) h[j] = 0.f;

    int time0 = dir ? (SEQ - 1) : 0;
    float a[10];
    {
        const float* A = g_A + (size_t)((dir*SEQ + time0)*10)*BATCH + b;
        #pragma unroll
        for (int i = 0; i < 10; i++) a[i] = A[i*BATCH];
    }

    for (int step = 0; step < SEQ; ++step) {
        int time = dir ? (SEQ - 1 - step) : step;

        float an[10];
        if (step < SEQ - 1) {
            int ntime = dir ? (SEQ - 2 - step) : (step + 1);
            const float* A = g_A + (size_t)((dir*SEQ + ntime)*10)*BATCH + b;
            #pragma unroll
            for (int i = 0; i < 10; i++) an[i] = A[i*BATCH];
        }

        float* gh = g_h + (size_t)(time*BATCH + b)*16 + dir*8;
        ((float4*)gh)[0] = make_float4(h[0], h[1], h[2], h[3]);
        ((float4*)gh)[1] = make_float4(h[4], h[5], h[6], h[7]);

        float zi = a[0], ri = a[1];
        #pragma unroll
        for (int i = 0; i < 8; i++) { zi += h[i]*wz[i]; ri += h[i]*wr[i]; }
        float z = 1.f / (1.f + __expf(-zi));
        float r = 1.f / (1.f + __expf(-ri));
        float rh[8];
        #pragma unroll
        for (int i = 0; i < 8; i++) rh[i] = r * h[i];
        float hc[8];
        #pragma unroll
        for (int j = 0; j < 8; j++) {
            float s = a[2 + j];
            #pragma unroll
            for (int i = 0; i < 8; i++) s += rh[i] * wh[i*8 + j];
            hc[j] = tanh_fast(s);
        }
        #pragma unroll
        for (int j = 0; j < 8; j++) h[j] += z * (hc[j] - h[j]);

        #pragma unroll
        for (int i = 0; i < 10; i++) a[i] = an[i];
    }
}

// ---------------------------------------------------------------------------
// Kernels 2a/2b: logits + log_softmax. Block = 64 rows x 1280 vocab.
// Warp owns 8 rows; thread owns 4 consecutive v. h stored in smem as (h,h)
// u64 dup pairs, layout [r][k]; fetched 2 k-steps at a time with LDS.128.
// Per v-tile iter: 16 LDG.128 + 64 LDS.128 + 256 FFMA2 (LSU/FMA2 = 0.31).
// ---------------------------------------------------------------------------
__global__ __launch_bounds__(256, 2) void k_sumexp(
    const float* __restrict__ Wout, const float* __restrict__ bout)
{
    __shared__ __align__(16) u64 h_pack[64*16];
    int tid = threadIdx.x;
    int by  = blockIdx.y;                 // rows by*64 .. by*64+63
    for (int i = tid; i < 64*16; i += 256) {
        float v = g_h[(size_t)by*1024 + i];
        h_pack[i] = pack2(v, v);
    }
    __syncthreads();

    int warp = tid >> 5, lane = tid & 31;
    const u64* hp = h_pack + warp*8*16;
    float part[8];
    #pragma unroll
    for (int r = 0; r < 8; r++) part[r] = 0.f;

    int vbase = blockIdx.x*1280 + lane*4;
    #pragma unroll 1
    for (int it = 0; it < 10; ++it) {
        int v = vbase + it*128;
        ulonglong2 bo = *(const ulonglong2*)(bout + v);
        u64 a0[8], a1[8];
        #pragma unroll
        for (int r = 0; r < 8; r++) { a0[r] = bo.x; a1[r] = bo.y; }
        #pragma unroll
        for (int kk = 0; kk < 16; kk += 2) {
            ulonglong2 w0 = *(const ulonglong2*)(Wout + (size_t)kk*VOCAB + v);
            ulonglong2 w1 = *(const ulonglong2*)(Wout + (size_t)(kk+1)*VOCAB + v);
            #pragma unroll
            for (int r = 0; r < 8; r++) {
                ulonglong2 h01 = *(const ulonglong2*)(hp + r*16 + kk);
                a0[r] = ffma2(w0.x, h01.x, a0[r]);
                a1[r] = ffma2(w0.y, h01.x, a1[r]);
                a0[r] = ffma2(w1.x, h01.y, a0[r]);
                a1[r] = ffma2(w1.y, h01.y, a1[r]);
            }
        }
        #pragma unroll
        for (int r = 0; r < 8; r++) {
            float e0, e1, e2, e3;
            unpack2(a0[r], e0, e1);
            unpack2(a1[r], e2, e3);
            part[r] += __expf(e0) + __expf(e1) + __expf(e2) + __expf(e3);
        }
    }
    #pragma unroll
    for (int r = 0; r < 8; r++) {
        float p = part[r];
        #pragma unroll
        for (int off = 16; off > 0; off >>= 1)
            p += __shfl_xor_sync(0xffffffffu, p, off);
        if (lane == 0) atomicAdd(&g_sum[by*64 + warp*8 + r], p);
    }
}

__global__ __launch_bounds__(256, 2) void k_write(
    const float* __restrict__ Wout, const float* __restrict__ bout,
    float* __restrict__ out)
{
    __shared__ __align__(16) u64 h_pack[64*16];
    __shared__ u64 nls_sh[64];
    int tid = threadIdx.x;
    int by  = blockIdx.y;
    for (int i = tid; i < 64*16; i += 256) {
        float v = g_h[(size_t)by*1024 + i];
        h_pack[i] = pack2(v, v);
    }
    if (tid < 64) {
        float nls = -__logf(g_sum[by*64 + tid]);
        nls_sh[tid] = pack2(nls, nls);
    }
    __syncthreads();

    int warp = tid >> 5, lane = tid & 31;
    const u64* hp = h_pack + warp*8*16;
    u64 nls[8];
    #pragma unroll
    for (int r = 0; r < 8; r++) nls[r] = nls_sh[warp*8 + r];

    int row_base = by*64 + warp*8;
    int vbase = blockIdx.x*1280 + lane*4;
    #pragma unroll 1
    for (int it = 0; it < 10; ++it) {
        int v = vbase + it*128;
        ulonglong2 bo = *(const ulonglong2*)(bout + v);
        u64 a0[8], a1[8];
        #pragma unroll
        for (int r = 0; r < 8; r++) { a0[r] = bo.x; a1[r] = bo.y; }
        #pragma unroll
        for (int kk = 0; kk < 16; kk += 2) {
            ulonglong2 w0 = *(const ulonglong2*)(Wout + (size_t)kk*VOCAB + v);
            ulonglong2 w1 = *(const ulonglong2*)(Wout + (size_t)(kk+1)*VOCAB + v);
            #pragma unroll
            for (int r = 0; r < 8; r++) {
                ulonglong2 h01 = *(const ulonglong2*)(hp + r*16 + kk);
                a0[r] = ffma2(w0.x, h01.x, a0[r]);
                a1[r] = ffma2(w0.y, h01.x, a1[r]);
                a0[r] = ffma2(w1.x, h01.y, a0[r]);
                a1[r] = ffma2(w1.y, h01.y, a1[r]);
            }
        }
        #pragma unroll
        for (int r = 0; r < 8; r++) {
            u64 o0 = fadd2(a0[r], nls[r]);
            u64 o1 = fadd2(a1[r], nls[r]);
            float* p = out + (size_t)(row_base + r)*VOCAB + v;
            asm volatile("st.global.cs.v2.u64 [%0], {%1, %2};"
                         :: "l"(p), "l"(o0), "l"(o1) : "memory");
        }
    }
}

// ---------------------------------------------------------------------------
extern "C" void kernel_launch(void* const* d_in, const int* in_sizes, int n_in,
                              void* d_out, int out_size)
{
    const int*   x    = (const int*)  d_in[0];
    const float* emb  = (const float*)d_in[1];
    const float* Wz1  = (const float*)d_in[2];  const float* bz1 = (const float*)d_in[3];
    const float* Wr1  = (const float*)d_in[4];  const float* br1 = (const float*)d_in[5];
    const float* Wh1  = (const float*)d_in[6];  const float* bh1 = (const float*)d_in[7];
    const float* Wz2  = (const float*)d_in[8];  const float* bz2 = (const float*)d_in[9];
    const float* Wr2  = (const float*)d_in[10]; const float* br2 = (const float*)d_in[11];
    const float* Wh2  = (const float*)d_in[12]; const float* bh2 = (const float*)d_in[13];
    const float* Wout = (const float*)d_in[14]; const float* bout= (const float*)d_in[15];
    float* out = (float*)d_out;

    k_pre<<<dim3(SEQ, 2), BATCH>>>(x, emb, Wz1, bz1, Wr1, br1, Wh1, bh1,
                                   Wz2, bz2, Wr2, br2, Wh2, bh2);
    k_gru<<<1, 128>>>(Wz1, Wr1, Wh1, Wz2, Wr2, Wh2);
    k_sumexp<<<dim3(25, 64), 256>>>(Wout, bout);
    k_write <<<dim3(25, 64), 256>>>(Wout, bout, out);
}

// round 5
// speedup vs baseline: 1.1849x; 1.0426x over previous
#include <cuda_runtime.h>
#include <math.h>

#define VOCAB 32000
#define EMB   32
#define HID   8
#define SEQ   64
#define BATCH 64
#define NROWS (SEQ*BATCH)   /* 4096 */

typedef unsigned long long u64;

__device__ __forceinline__ u64 ffma2(u64 a, u64 b, u64 c) {
    u64 d; asm("fma.rn.f32x2 %0, %1, %2, %3;" : "=l"(d) : "l"(a), "l"(b), "l"(c)); return d;
}
__device__ __forceinline__ u64 fadd2(u64 a, u64 b) {
    u64 d; asm("add.rn.f32x2 %0, %1, %2;" : "=l"(d) : "l"(a), "l"(b)); return d;
}
__device__ __forceinline__ u64 pack2(float x, float y) {
    u64 d; asm("mov.b64 %0, {%1, %2};" : "=l"(d) : "r"(__float_as_uint(x)), "r"(__float_as_uint(y))); return d;
}
__device__ __forceinline__ void unpack2(u64 v, float& x, float& y) {
    unsigned a, b; asm("mov.b64 {%0, %1}, %2;" : "=r"(a), "=r"(b) : "l"(v));
    x = __uint_as_float(a); y = __uint_as_float(b);
}
__device__ __forceinline__ float tanh_fast(float x) {
    float y; asm("tanh.approx.f32 %0, %1;" : "=f"(y) : "f"(x)); return y;
}

// Scratch (device globals: allocation-free rule)
__device__ float g_A[2*SEQ*BATCH*10];
__device__ float g_h[NROWS*16];
__device__ float g_sum[NROWS];

// ---------------------------------------------------------------------------
// Kernel 0: embedding gather + input-projection precompute
// ---------------------------------------------------------------------------
__global__ __launch_bounds__(64) void k_pre(
    const int*   __restrict__ x,   const float* __restrict__ emb,
    const float* __restrict__ Wz1, const float* __restrict__ bz1,
    const float* __restrict__ Wr1, const float* __restrict__ br1,
    const float* __restrict__ Wh1, const float* __restrict__ bh1,
    const float* __restrict__ Wz2, const float* __restrict__ bz2,
    const float* __restrict__ Wr2, const float* __restrict__ br2,
    const float* __restrict__ Wh2, const float* __restrict__ bh2)
{
    int t = blockIdx.x, dir = blockIdx.y, b = threadIdx.x;
    int gid = (dir*SEQ + t)*BATCH + b;
    if (gid < NROWS) g_sum[gid] = 0.f;

    const float* Wz = dir ? Wz2 : Wz1;
    const float* Wr = dir ? Wr2 : Wr1;
    const float* Wh = dir ? Wh2 : Wh1;
    float az = (dir ? bz2 : bz1)[0];
    float ar = (dir ? br2 : br1)[0];
    const float* bh = dir ? bh2 : bh1;
    float ah[8];
    #pragma unroll
    for (int j = 0; j < 8; j++) ah[j] = bh[j];

    int idx = x[t*BATCH + b];
    const float* e = emb + (size_t)idx * EMB;
    float ev[32];
    #pragma unroll
    for (int k = 0; k < 8; k++) {
        float4 v4 = ((const float4*)e)[k];
        ev[4*k+0] = v4.x; ev[4*k+1] = v4.y; ev[4*k+2] = v4.z; ev[4*k+3] = v4.w;
    }
    #pragma unroll
    for (int k = 0; k < 32; k++) {
        float evk = ev[k];
        az += evk * Wz[8 + k];
        ar += evk * Wr[8 + k];
        #pragma unroll
        for (int j = 0; j < 8; j++) ah[j] += evk * Wh[(8 + k)*8 + j];
    }
    float* Ab = g_A + (size_t)((dir*SEQ + t)*10)*BATCH + b;
    Ab[0] = az;
    Ab[BATCH] = ar;
    #pragma unroll
    for (int j = 0; j < 8; j++) Ab[(2 + j)*BATCH] = ah[j];
}

// ---------------------------------------------------------------------------
// Kernel 1: serial GRU (simple R1 form), 2 dirs x 64 batches.
// ---------------------------------------------------------------------------
__global__ __launch_bounds__(128) void k_gru(
    const float* __restrict__ Wz1, const float* __restrict__ Wr1, const float* __restrict__ Wh1,
    const float* __restrict__ Wz2, const float* __restrict__ Wr2, const float* __restrict__ Wh2)
{
    int tid = threadIdx.x;
    int dir = tid >> 6, b = tid & 63;
    const float* Wz = dir ? Wz2 : Wz1;
    const float* Wr = dir ? Wr2 : Wr1;
    const float* Wh = dir ? Wh2 : Wh1;

    float wz[8], wr[8], wh[64];
    #pragma unroll
    for (int i = 0; i < 8; i++) { wz[i] = Wz[i]; wr[i] = Wr[i]; }
    #pragma unroll
    for (int i = 0; i < 64; i++) wh[i] = Wh[i];

    float h[8];
    #pragma unroll
    for (int j = 0; j < 8; j++) h[j] = 0.f;

    for (int step = 0; step < SEQ; ++step) {
        int time = dir ? (SEQ - 1 - step) : step;

        float* gh = g_h + (size_t)(time*BATCH + b)*16 + dir*8;
        ((float4*)gh)[0] = make_float4(h[0], h[1], h[2], h[3]);
        ((float4*)gh)[1] = make_float4(h[4], h[5], h[6], h[7]);

        const float* A = g_A + (size_t)((dir*SEQ + time)*10)*BATCH + b;
        float zi = A[0], ri = A[BATCH];
        #pragma unroll
        for (int i = 0; i < 8; i++) { zi += h[i]*wz[i]; ri += h[i]*wr[i]; }
        float z = 1.f / (1.f + __expf(-zi));
        float r = 1.f / (1.f + __expf(-ri));
        float hc[8];
        #pragma unroll
        for (int j = 0; j < 8; j++) {
            float s = A[(2 + j)*BATCH];
            #pragma unroll
            for (int i = 0; i < 8; i++) s += (r*h[i]) * wh[i*8 + j];
            hc[j] = tanh_fast(s);
        }
        #pragma unroll
        for (int j = 0; j < 8; j++) h[j] += z * (hc[j] - h[j]);
    }
}

// ---------------------------------------------------------------------------
// Kernel 2a: sumexp pass. FFMA2, 8 rows/warp, LDS.128 h-pairs.
// NO register cap (spills are worse than low occupancy here).
// ---------------------------------------------------------------------------
__global__ __launch_bounds__(256) void k_sumexp(
    const float* __restrict__ Wout, const float* __restrict__ bout)
{
    __shared__ __align__(16) u64 h_pack[64*16];
    int tid = threadIdx.x;
    int by  = blockIdx.y;                 // rows by*64 .. by*64+63
    for (int i = tid; i < 64*16; i += 256) {
        float v = g_h[(size_t)by*1024 + i];
        h_pack[i] = pack2(v, v);
    }
    __syncthreads();

    int warp = tid >> 5, lane = tid & 31;
    const u64* hp = h_pack + warp*8*16;
    float part[8];
    #pragma unroll
    for (int r = 0; r < 8; r++) part[r] = 0.f;

    int vbase = blockIdx.x*1280 + lane*4;
    for (int it = 0; it < 10; ++it) {
        int v = vbase + it*128;
        ulonglong2 bo = *(const ulonglong2*)(bout + v);
        u64 a0[8], a1[8];
        #pragma unroll
        for (int r = 0; r < 8; r++) { a0[r] = bo.x; a1[r] = bo.y; }
        #pragma unroll
        for (int kk = 0; kk < 16; kk += 2) {
            ulonglong2 w0 = *(const ulonglong2*)(Wout + (size_t)kk*VOCAB + v);
            ulonglong2 w1 = *(const ulonglong2*)(Wout + (size_t)(kk+1)*VOCAB + v);
            #pragma unroll
            for (int r = 0; r < 8; r++) {
                ulonglong2 h01 = *(const ulonglong2*)(hp + r*16 + kk);
                a0[r] = ffma2(w0.x, h01.x, a0[r]);
                a1[r] = ffma2(w0.y, h01.x, a1[r]);
                a0[r] = ffma2(w1.x, h01.y, a0[r]);
                a1[r] = ffma2(w1.y, h01.y, a1[r]);
            }
        }
        #pragma unroll
        for (int r = 0; r < 8; r++) {
            float e0, e1, e2, e3;
            unpack2(a0[r], e0, e1);
            unpack2(a1[r], e2, e3);
            part[r] += (__expf(e0) + __expf(e1)) + (__expf(e2) + __expf(e3));
        }
    }
    #pragma unroll
    for (int r = 0; r < 8; r++) {
        float p = part[r];
        #pragma unroll
        for (int off = 16; off > 0; off >>= 1)
            p += __shfl_xor_sync(0xffffffffu, p, off);
        if (lane == 0) atomicAdd(&g_sum[by*64 + warp*8 + r], p);
    }
}

// ---------------------------------------------------------------------------
// Kernel 2b: write pass — identical to round 4 (best measured: 131.5us).
// ---------------------------------------------------------------------------
__global__ __launch_bounds__(256, 2) void k_write(
    const float* __restrict__ Wout, const float* __restrict__ bout,
    float* __restrict__ out)
{
    __shared__ __align__(16) u64 h_pack[64*16];
    __shared__ u64 nls_sh[64];
    int tid = threadIdx.x;
    int by  = blockIdx.y;
    for (int i = tid; i < 64*16; i += 256) {
        float v = g_h[(size_t)by*1024 + i];
        h_pack[i] = pack2(v, v);
    }
    if (tid < 64) {
        float nls = -__logf(g_sum[by*64 + tid]);
        nls_sh[tid] = pack2(nls, nls);
    }
    __syncthreads();

    int warp = tid >> 5, lane = tid & 31;
    const u64* hp = h_pack + warp*8*16;
    u64 nls[8];
    #pragma unroll
    for (int r = 0; r < 8; r++) nls[r] = nls_sh[warp*8 + r];

    int row_base = by*64 + warp*8;
    int vbase = blockIdx.x*1280 + lane*4;
    #pragma unroll 1
    for (int it = 0; it < 10; ++it) {
        int v = vbase + it*128;
        ulonglong2 bo = *(const ulonglong2*)(bout + v);
        u64 a0[8], a1[8];
        #pragma unroll
        for (int r = 0; r < 8; r++) { a0[r] = bo.x; a1[r] = bo.y; }
        #pragma unroll
        for (int kk = 0; kk < 16; kk += 2) {
            ulonglong2 w0 = *(const ulonglong2*)(Wout + (size_t)kk*VOCAB + v);
            ulonglong2 w1 = *(const ulonglong2*)(Wout + (size_t)(kk+1)*VOCAB + v);
            #pragma unroll
            for (int r = 0; r < 8; r++) {
                ulonglong2 h01 = *(const ulonglong2*)(hp + r*16 + kk);
                a0[r] = ffma2(w0.x, h01.x, a0[r]);
                a1[r] = ffma2(w0.y, h01.x, a1[r]);
                a0[r] = ffma2(w1.x, h01.y, a0[r]);
                a1[r] = ffma2(w1.y, h01.y, a1[r]);
            }
        }
        #pragma unroll
        for (int r = 0; r < 8; r++) {
            u64 o0 = fadd2(a0[r], nls[r]);
            u64 o1 = fadd2(a1[r], nls[r]);
            float* p = out + (size_t)(row_base + r)*VOCAB + v;
            asm volatile("st.global.cs.v2.u64 [%0], {%1, %2};"
                         :: "l"(p), "l"(o0), "l"(o1) : "memory");
        }
    }
}

// ---------------------------------------------------------------------------
extern "C" void kernel_launch(void* const* d_in, const int* in_sizes, int n_in,
                              void* d_out, int out_size)
{
    const int*   x    = (const int*)  d_in[0];
    const float* emb  = (const float*)d_in[1];
    const float* Wz1  = (const float*)d_in[2];  const float* bz1 = (const float*)d_in[3];
    const float* Wr1  = (const float*)d_in[4];  const float* br1 = (const float*)d_in[5];
    const float* Wh1  = (const float*)d_in[6];  const float* bh1 = (const float*)d_in[7];
    const float* Wz2  = (const float*)d_in[8];  const float* bz2 = (const float*)d_in[9];
    const float* Wr2  = (const float*)d_in[10]; const float* br2 = (const float*)d_in[11];
    const float* Wh2  = (const float*)d_in[12]; const float* bh2 = (const float*)d_in[13];
    const float* Wout = (const float*)d_in[14]; const float* bout= (const float*)d_in[15];
    float* out = (float*)d_out;

    k_pre<<<dim3(SEQ, 2), BATCH>>>(x, emb, Wz1, bz1, Wr1, br1, Wh1, bh1,
                                   Wz2, bz2, Wr2, br2, Wh2, bh2);
    k_gru<<<1, 128>>>(Wz1, Wr1, Wh1, Wz2, Wr2, Wh2);
    k_sumexp<<<dim3(25, 64), 256>>>(Wout, bout);
    k_write <<<dim3(25, 64), 256>>>(Wout, bout, out);
}